// round 4
// baseline (speedup 1.0000x reference)
#include <cuda_runtime.h>

// Shapes (fixed by the problem)
#define B_    4
#define CIN   64
#define COUT  64
#define H_    512
#define W_    512
#define WDIM  512
#define TAPS  9
#define CC    8      // cin chunk per smem stage
#define TW    128    // output tile width per block

// Folded per-batch weights: [b][cin][tap][cout]
__device__ float g_w[B_ * CIN * TAPS * COUT];

// ---------------------------------------------------------------------------
// Packed f32x2 helpers (sm_100+; FFMA2 is reachable only via PTX)
// ---------------------------------------------------------------------------
__device__ __forceinline__ unsigned long long f2_fma(unsigned long long a,
                                                     unsigned long long b,
                                                     unsigned long long c) {
    unsigned long long d;
    asm("fma.rn.f32x2 %0, %1, %2, %3;" : "=l"(d) : "l"(a), "l"(b), "l"(c));
    return d;
}
__device__ __forceinline__ unsigned long long f2_dup(float v) {
    unsigned long long d;
    asm("mov.b64 %0, {%1, %1};" : "=l"(d) : "f"(v));
    return d;
}
__device__ __forceinline__ void f2_unpack(unsigned long long p, float& lo, float& hi) {
    asm("mov.b64 {%0, %1}, %2;" : "=f"(lo), "=f"(hi) : "l"(p));
}

// ---------------------------------------------------------------------------
// Phase 1: style = w @ (rc_dense * mod_w) + mod_b + 1
//          wt    = rc_conv * conv_w * style[cin]
//          d     = rsqrt(sum_{cin,tap} wt^2 + 1e-8)   (per cout)
//          g_w[b][cin][tap][cout] = wt * d
// conv_w layout: [kh][kw][cin][cout]  (K,K,CIN,COUT)
// ---------------------------------------------------------------------------
__global__ void prep_kernel(const float* __restrict__ w,
                            const float* __restrict__ conv_w,
                            const float* __restrict__ mod_w,
                            const float* __restrict__ mod_b) {
    __shared__ float s_style[CIN];
    __shared__ float s_d[COUT];
    const int b   = blockIdx.x;
    const int tid = threadIdx.x;
    const float rc_dense = 0.04419417382415922f;  // 1/sqrt(512)
    const float rc_conv  = 1.0f / 24.0f;          // 1/sqrt(3*3*64)

    if (tid < CIN) {
        float s = 0.f;
        const float* wb = w + b * WDIM;
        #pragma unroll 8
        for (int d = 0; d < WDIM; ++d)
            s += wb[d] * mod_w[d * CIN + tid];
        s_style[tid] = s * rc_dense + mod_b[tid] + 1.0f;
    }
    __syncthreads();

    if (tid < COUT) {  // tid == cout
        float ss = 0.f;
        for (int cin = 0; cin < CIN; ++cin) {
            float st = rc_conv * s_style[cin];
            #pragma unroll
            for (int tap = 0; tap < TAPS; ++tap) {
                float v = conv_w[(tap * CIN + cin) * COUT + tid] * st;
                ss += v * v;
            }
        }
        s_d[tid] = rsqrtf(ss + 1e-8f);
    }
    __syncthreads();

    float* gw = g_w + b * CIN * TAPS * COUT;
    for (int idx = tid; idx < CIN * TAPS * COUT; idx += blockDim.x) {
        int cout = idx & (COUT - 1);
        int tap  = (idx >> 6) % TAPS;
        int cin  = idx / (TAPS * COUT);
        gw[idx] = rc_conv * conv_w[(tap * CIN + cin) * COUT + cout]
                * s_style[cin] * s_d[cout];
    }
}

// ---------------------------------------------------------------------------
// Phase 2: direct 3x3 SAME conv, grouped by batch, packed-f32x2 mainloop.
//
// Block: 256 threads = 8 cout-groups x 32 pixel-lanes.
// Thread: 4 cout-PAIRS x 4 pixels (stride 32) -> 16 f32x2 accumulators.
// Packing is over cout pairs:
//   - weight pair (w[co], w[co+1]) loads as ONE broadcast LDS.64 from the
//     [cin][tap][cout] smem layout (adjacent couts, 8B-aligned) and feeds
//     FFMA2 directly — no unpack.
//   - x scalar is duplicated into both lanes once per (kw, pixel) via mov.b64
//     (ALU pipe, off the FMA critical path).
// Per cin per warp: 144 FFMA2 + 36 LDS.64 + 12 LDS.32 + 12 mov64
//   -> FMA pipe ~2.04e6 chip-cycles, LDS pipe ~1.36e6 -> FMA-bound.
// ---------------------------------------------------------------------------
__global__ void __launch_bounds__(256, 2)
conv_kernel(const float* __restrict__ x, float* __restrict__ out) {
    __shared__ float sx[CC][3][TW + 2];
    __shared__ float sw[CC][TAPS][COUT];

    const int tid     = threadIdx.x;
    const int lane    = tid & 31;   // pixel lane
    const int cg      = tid >> 5;   // cout group 0..7 (couts cg*8 .. cg*8+7)
    const int colbase = blockIdx.x * TW;
    const int row     = blockIdx.y;
    const int b       = blockIdx.z;

    unsigned long long acc[4][4];   // [cout-pair][pixel]
    #pragma unroll
    for (int p = 0; p < 4; ++p)
        #pragma unroll
        for (int j = 0; j < 4; ++j) acc[p][j] = 0ull;

    const float* xb = x + (size_t)b * CIN * H_ * W_;
    const float* gw = g_w + b * CIN * TAPS * COUT;

    for (int c0 = 0; c0 < CIN; c0 += CC) {
        // --- stage x chunk: CC cin x 3 rows x (TW+2) cols, zero-padded ---
        for (int idx = tid; idx < CC * 3 * (TW + 2); idx += 256) {
            int cc  = idx / (3 * (TW + 2));
            int rem = idx % (3 * (TW + 2));
            int kh  = rem / (TW + 2);
            int ci  = rem % (TW + 2);
            int grow = row + kh - 1;
            int gcol = colbase + ci - 1;
            float v = 0.f;
            if ((unsigned)grow < (unsigned)H_ && (unsigned)gcol < (unsigned)W_)
                v = xb[((size_t)(c0 + cc) * H_ + grow) * W_ + gcol];
            sx[cc][kh][ci] = v;
        }
        // --- stage weight chunk: contiguous ([cin][tap][cout] layout) ---
        {
            const float* gwc = gw + c0 * TAPS * COUT;
            float* swl = &sw[0][0][0];
            for (int idx = tid; idx < CC * TAPS * COUT; idx += 256)
                swl[idx] = gwc[idx];
        }
        __syncthreads();

        for (int cc = 0; cc < CC; ++cc) {
            #pragma unroll
            for (int kh = 0; kh < 3; ++kh) {
                // x window: duplicate each scalar into both f32x2 lanes
                unsigned long long xx[3][4];
                #pragma unroll
                for (int kw = 0; kw < 3; ++kw)
                    #pragma unroll
                    for (int j = 0; j < 4; ++j)
                        xx[kw][j] = f2_dup(sx[cc][kh][lane + 32 * j + kw]);

                #pragma unroll
                for (int p = 0; p < 4; ++p) {
                    // broadcast LDS.64: weights for cout pair (cg*8+2p, +1)
                    const unsigned long long* wp =
                        (const unsigned long long*)&sw[cc][kh * 3][cg * 8 + 2 * p];
                    unsigned long long w0 = wp[0 * (COUT / 2)];
                    unsigned long long w1 = wp[1 * (COUT / 2)];
                    unsigned long long w2 = wp[2 * (COUT / 2)];
                    #pragma unroll
                    for (int j = 0; j < 4; ++j) {
                        acc[p][j] = f2_fma(xx[0][j], w0, acc[p][j]);
                        acc[p][j] = f2_fma(xx[1][j], w1, acc[p][j]);
                        acc[p][j] = f2_fma(xx[2][j], w2, acc[p][j]);
                    }
                }
            }
        }
        __syncthreads();
    }

    // --- write out[b][cout][row][col], coalesced per warp ---
    #pragma unroll
    for (int p = 0; p < 4; ++p) {
        int cout0 = cg * 8 + 2 * p;
        float* o0 = out + (((size_t)b * COUT + cout0)     * H_ + row) * W_
                  + colbase + lane;
        float* o1 = out + (((size_t)b * COUT + cout0 + 1) * H_ + row) * W_
                  + colbase + lane;
        #pragma unroll
        for (int j = 0; j < 4; ++j) {
            float lo, hi;
            f2_unpack(acc[p][j], lo, hi);
            o0[32 * j] = lo;
            o1[32 * j] = hi;
        }
    }
}

// ---------------------------------------------------------------------------
// Harness entry. Inputs (metadata order): x, w, conv_w, mod_w, mod_b.
// ---------------------------------------------------------------------------
extern "C" void kernel_launch(void* const* d_in, const int* in_sizes, int n_in,
                              void* d_out, int out_size) {
    const float* x      = (const float*)d_in[0];
    const float* w      = (const float*)d_in[1];
    const float* conv_w = (const float*)d_in[2];
    const float* mod_w  = (const float*)d_in[3];
    const float* mod_b  = (const float*)d_in[4];
    float* out = (float*)d_out;

    prep_kernel<<<B_, 256>>>(w, conv_w, mod_w, mod_b);
    conv_kernel<<<dim3(W_ / TW, H_, B_), 256>>>(x, out);
    (void)in_sizes; (void)n_in; (void)out_size;
}

// round 5
// speedup vs baseline: 1.4068x; 1.4068x over previous
#include <cuda_runtime.h>
#include <cstdint>

// Shapes (fixed by the problem)
#define B_    4
#define CIN   64
#define COUT  64
#define H_    512
#define W_    512
#define WDIM  512
#define TAPS  9
#define CC    4            // cins per pipeline chunk
#define NCHUNK (CIN/CC)    // 16
#define TW    256          // output tile width per block
#define SX_ROW 264         // staged floats per x row: gcol in [colbase-4, colbase+260)
#define SX_BUF (CC*3*SX_ROW)   // 3168 floats
#define SW_BUF (CC*TAPS*COUT)  // 2304 floats

// Folded per-batch weights: [b][cin][tap][cout]
__device__ float g_w[B_ * CIN * TAPS * COUT];

// ---------------------------------------------------------------------------
// helpers
// ---------------------------------------------------------------------------
__device__ __forceinline__ unsigned long long f2_fma(unsigned long long a,
                                                     unsigned long long b,
                                                     unsigned long long c) {
    unsigned long long d;
    asm("fma.rn.f32x2 %0, %1, %2, %3;" : "=l"(d) : "l"(a), "l"(b), "l"(c));
    return d;
}
__device__ __forceinline__ unsigned long long f2_dup(float v) {
    unsigned long long d;
    asm("mov.b64 %0, {%1, %1};" : "=l"(d) : "f"(v));
    return d;
}
__device__ __forceinline__ void f2_unpack(unsigned long long p, float& lo, float& hi) {
    asm("mov.b64 {%0, %1}, %2;" : "=f"(lo), "=f"(hi) : "l"(p));
}
// 16B-granule XOR swizzle: flip bit4 based on bit7 (conflict-free for the
// 32B-strided per-lane access pattern below). Applied identically on the
// cp.async store side and the LDS side; preserves 16B alignment.
__device__ __forceinline__ uint32_t swz(uint32_t a) { return a ^ ((a >> 3) & 16u); }

__device__ __forceinline__ void cp16(uint32_t dst, const float* src, bool pred) {
    int sz = pred ? 16 : 0;
    asm volatile("cp.async.cg.shared.global [%0], [%1], 16, %2;"
                 :: "r"(dst), "l"(src), "r"(sz));
}
__device__ __forceinline__ void cp_commit() { asm volatile("cp.async.commit_group;"); }
__device__ __forceinline__ void cp_wait0()  { asm volatile("cp.async.wait_group 0;"); }

__device__ __forceinline__ float4 lds128(uint32_t a) {
    float4 v;
    asm volatile("ld.shared.v4.f32 {%0,%1,%2,%3}, [%4];"
                 : "=f"(v.x), "=f"(v.y), "=f"(v.z), "=f"(v.w) : "r"(a));
    return v;
}
__device__ __forceinline__ float lds32(uint32_t a) {
    float v;
    asm volatile("ld.shared.f32 %0, [%1];" : "=f"(v) : "r"(a));
    return v;
}
__device__ __forceinline__ unsigned long long lds64(uint32_t a) {
    unsigned long long v;
    asm volatile("ld.shared.b64 %0, [%1];" : "=l"(v) : "r"(a));
    return v;
}

// ---------------------------------------------------------------------------
// Phase 1: style / demod / fold weights into g_w[b][cin][tap][cout]
// conv_w layout: [kh][kw][cin][cout]
// ---------------------------------------------------------------------------
__global__ void prep_kernel(const float* __restrict__ w,
                            const float* __restrict__ conv_w,
                            const float* __restrict__ mod_w,
                            const float* __restrict__ mod_b) {
    __shared__ float s_style[CIN];
    __shared__ float s_d[COUT];
    const int b   = blockIdx.x;
    const int tid = threadIdx.x;
    const float rc_dense = 0.04419417382415922f;  // 1/sqrt(512)
    const float rc_conv  = 1.0f / 24.0f;          // 1/sqrt(3*3*64)

    if (tid < CIN) {
        float s = 0.f;
        const float* wb = w + b * WDIM;
        #pragma unroll 8
        for (int d = 0; d < WDIM; ++d)
            s += wb[d] * mod_w[d * CIN + tid];
        s_style[tid] = s * rc_dense + mod_b[tid] + 1.0f;
    }
    __syncthreads();

    if (tid < COUT) {
        float ss = 0.f;
        for (int cin = 0; cin < CIN; ++cin) {
            float st = rc_conv * s_style[cin];
            #pragma unroll
            for (int tap = 0; tap < TAPS; ++tap) {
                float v = conv_w[(tap * CIN + cin) * COUT + tid] * st;
                ss += v * v;
            }
        }
        s_d[tid] = rsqrtf(ss + 1e-8f);
    }
    __syncthreads();

    float* gw = g_w + b * CIN * TAPS * COUT;
    for (int idx = tid; idx < CIN * TAPS * COUT; idx += blockDim.x) {
        int cout = idx & (COUT - 1);
        int tap  = (idx >> 6) % TAPS;
        int cin  = idx / (TAPS * COUT);
        gw[idx] = rc_conv * conv_w[(tap * CIN + cin) * COUT + cout]
                * s_style[cin] * s_d[cout];
    }
}

// ---------------------------------------------------------------------------
// Phase 2: direct 3x3 SAME conv, grouped by batch.
// Block: 256 threads = 8 warps; warp = one cout-group of 8 couts over all
// TW=256 pixels of one row. Thread: 8 CONSECUTIVE pixels x 4 cout-pairs
// (FFMA2 packs cout pairs) -> 32 f32x2 accumulators.
// x per (cin,kh): 10-float sliding window = 2xLDS.128 + 2xLDS.32 (swizzled,
// conflict-free). w: broadcast LDS.64 per (tap, cout-pair).
// cp.async double-buffered staging, one bar.sync per chunk.
// ---------------------------------------------------------------------------
__global__ void __launch_bounds__(256, 2)
conv_kernel(const float* __restrict__ x, float* __restrict__ out) {
    __shared__ __align__(16) float sxs[2][SX_BUF];
    __shared__ __align__(16) float sws[2][SW_BUF];

    const int tid     = threadIdx.x;
    const int lane    = tid & 31;
    const int cg      = tid >> 5;          // cout group (warp id)
    const int colbase = blockIdx.x * TW;
    const int row     = blockIdx.y;
    const int b       = blockIdx.z;

    const float* xb = x + (size_t)b * CIN * H_ * W_;
    const float* gw = g_w + b * CIN * TAPS * COUT;

    const uint32_t sx_base = (uint32_t)__cvta_generic_to_shared(&sxs[0][0]);
    const uint32_t sw_base = (uint32_t)__cvta_generic_to_shared(&sws[0][0]);

    unsigned long long acc[4][8];          // [cout-pair][pixel]
    #pragma unroll
    for (int p = 0; p < 4; ++p)
        #pragma unroll
        for (int j = 0; j < 8; ++j) acc[p][j] = 0ull;

    // --- staging: one CC-cin chunk into buffer buf ---
    auto stage = [&](int chunk, int buf) {
        const uint32_t sxb = sx_base + (uint32_t)buf * (SX_BUF * 4);
        const uint32_t swb = sw_base + (uint32_t)buf * (SW_BUF * 4);
        const int c0 = chunk * CC;
        // x: CC cin x 3 rows x 66 16B-chunks, zero-filled at borders
        for (int idx = tid; idx < CC * 3 * 66; idx += 256) {
            int c16 = idx % 66;
            int t   = idx / 66;
            int kh  = t % 3;
            int cc  = t / 3;
            int grow = row + kh - 1;
            int g0   = colbase - 4 + c16 * 4;
            bool ok  = ((unsigned)grow < (unsigned)H_) &&
                       ((unsigned)g0   < (unsigned)(W_ - 3));
            int sgr = ((unsigned)grow < (unsigned)H_) ? grow : 0;
            int sg0 = ok ? g0 : 0;
            const float* src = xb + ((size_t)(c0 + cc) * H_ + sgr) * W_ + sg0;
            uint32_t dst = swz(sxb + (uint32_t)(((cc * 3 + kh) * SX_ROW + c16 * 4) * 4));
            cp16(dst, src, ok);
        }
        // w: contiguous [cin][tap][cout]
        const float* wsrc = gw + c0 * TAPS * COUT;
        for (int idx = tid; idx < SW_BUF / 4; idx += 256)
            cp16(swb + (uint32_t)(idx * 16), wsrc + idx * 4, true);
    };

    stage(0, 0);
    cp_commit();

    for (int c = 0; c < NCHUNK; ++c) {
        cp_wait0();
        __syncthreads();                   // chunk c staged & visible; buf c^1 free
        if (c + 1 < NCHUNK) stage(c + 1, (c + 1) & 1);
        cp_commit();

        const int buf = c & 1;
        const uint32_t sxb = sx_base + (uint32_t)buf * (SX_BUF * 4);
        const uint32_t swb = sw_base + (uint32_t)buf * (SW_BUF * 4);

        #pragma unroll
        for (int cc = 0; cc < CC; ++cc) {
            #pragma unroll
            for (int kh = 0; kh < 3; ++kh) {
                // 10-float window: ci = 3+8*lane .. 12+8*lane
                uint32_t rb = sxb + (uint32_t)(((cc * 3 + kh) * SX_ROW) * 4) + lane * 32;
                float  s0 = lds32 (swz(rb + 12));
                float4 va = lds128(swz(rb + 16));
                float4 vb = lds128(swz(rb + 32));
                float  s1 = lds32 (swz(rb + 48));
                unsigned long long xx[10];
                xx[0] = f2_dup(s0);
                xx[1] = f2_dup(va.x); xx[2] = f2_dup(va.y);
                xx[3] = f2_dup(va.z); xx[4] = f2_dup(va.w);
                xx[5] = f2_dup(vb.x); xx[6] = f2_dup(vb.y);
                xx[7] = f2_dup(vb.z); xx[8] = f2_dup(vb.w);
                xx[9] = f2_dup(s1);

                #pragma unroll
                for (int p = 0; p < 4; ++p) {
                    uint32_t wb = swb + (uint32_t)((((cc * 9 + kh * 3) * COUT)
                                                   + cg * 8 + 2 * p) * 4);
                    unsigned long long w0 = lds64(wb);              // kw=0, broadcast
                    unsigned long long w1 = lds64(wb + COUT * 4);   // kw=1
                    unsigned long long w2 = lds64(wb + 2 * COUT * 4);
                    #pragma unroll
                    for (int j = 0; j < 8; ++j) {
                        acc[p][j] = f2_fma(xx[j],     w0, acc[p][j]);
                        acc[p][j] = f2_fma(xx[j + 1], w1, acc[p][j]);
                        acc[p][j] = f2_fma(xx[j + 2], w2, acc[p][j]);
                    }
                }
            }
        }
    }

    // --- epilogue: out[b][cout][row][col], STG.128, px consecutive per thread ---
    size_t obase = ((size_t)b * COUT) * H_ * W_ + (size_t)row * W_
                 + colbase + lane * 8;
    #pragma unroll
    for (int p = 0; p < 4; ++p) {
        int cout0 = cg * 8 + 2 * p;
        float* o0 = out + obase + (size_t)cout0 * (H_ * W_);
        float* o1 = o0 + (size_t)(H_ * W_);
        float lo[8], hi[8];
        #pragma unroll
        for (int j = 0; j < 8; ++j) f2_unpack(acc[p][j], lo[j], hi[j]);
        reinterpret_cast<float4*>(o0)[0] = make_float4(lo[0], lo[1], lo[2], lo[3]);
        reinterpret_cast<float4*>(o0)[1] = make_float4(lo[4], lo[5], lo[6], lo[7]);
        reinterpret_cast<float4*>(o1)[0] = make_float4(hi[0], hi[1], hi[2], hi[3]);
        reinterpret_cast<float4*>(o1)[1] = make_float4(hi[4], hi[5], hi[6], hi[7]);
    }
}

// ---------------------------------------------------------------------------
// Harness entry. Inputs (metadata order): x, w, conv_w, mod_w, mod_b.
// ---------------------------------------------------------------------------
extern "C" void kernel_launch(void* const* d_in, const int* in_sizes, int n_in,
                              void* d_out, int out_size) {
    const float* x      = (const float*)d_in[0];
    const float* w      = (const float*)d_in[1];
    const float* conv_w = (const float*)d_in[2];
    const float* mod_w  = (const float*)d_in[3];
    const float* mod_b  = (const float*)d_in[4];
    float* out = (float*)d_out;

    prep_kernel<<<B_, 256>>>(w, conv_w, mod_w, mod_b);
    conv_kernel<<<dim3(W_ / TW, H_, B_), 256>>>(x, out);
    (void)in_sizes; (void)n_in; (void)out_size;
}